// round 4
// baseline (speedup 1.0000x reference)
#include <cuda_runtime.h>

typedef unsigned long long u64;

#define NB   4
#define SS   512
#define DD   64
#define NH   8
#define NROWS (NB*SS)      // 2048
#define DT_F 0.25f

// Persistent device scratch (no allocations allowed)
__device__ __align__(16) float g_y[NROWS*DD];
__device__ __align__(16) float g_ytmp[NROWS*DD];
__device__ __align__(16) float g_kst[6*NROWS*DD];
__device__ __align__(16) float g_q[NROWS*DD];
__device__ __align__(16) float g_kk[NROWS*DD];
__device__ __align__(16) float g_vv[NROWS*DD];
__device__ __align__(16) float g_att[NROWS*DD];

struct StageCtl {
    float ac[6];
    int   nc;
    int   stage;
    int   do_qkv;
    int   write_y;
};

// ---------------- f32x2 helpers (packed fp32, sm_100a) ----------------
__device__ __forceinline__ u64 pk(float x, float y) {
    u64 r; asm("mov.b64 %0,{%1,%2};" : "=l"(r) : "f"(x), "f"(y)); return r;
}
__device__ __forceinline__ void unpk(u64 v, float& x, float& y) {
    asm("mov.b64 {%0,%1},%2;" : "=f"(x), "=f"(y) : "l"(v));
}
__device__ __forceinline__ u64 splat(float x) {
    u64 r; asm("mov.b64 %0,{%1,%1};" : "=l"(r) : "f"(x)); return r;
}
__device__ __forceinline__ void fma2(u64& d, u64 a, u64 b) {
    asm("fma.rn.f32x2 %0,%1,%2,%0;" : "+l"(d) : "l"(a), "l"(b));
}
__device__ __forceinline__ u64 add2(u64 a, u64 b) {
    u64 d; asm("add.rn.f32x2 %0,%1,%2;" : "=l"(d) : "l"(a), "l"(b)); return d;
}
__device__ __forceinline__ u64 mul2(u64 a, u64 b) {
    u64 d; asm("mul.rn.f32x2 %0,%1,%2;" : "=l"(d) : "l"(a), "l"(b)); return d;
}

// ---------------------------------------------------------------------------
__global__ void __launch_bounds__(256) copy_out_kernel(float* __restrict__ out) {
    int i = blockIdx.x * blockDim.x + threadIdx.x;
    ((float4*)out)[i] = ((const float4*)g_y)[i];
}

// ---------------------------------------------------------------------------
// qkv GEMV over row-pair-packed activations sX2 ([4 pairs][64] u64).
// Thread (p = tid>>6, c = tid&63): q,k,v column c of rows {2p, 2p+1}.
__device__ __forceinline__ void qkv_phase(
    const u64* sX2, int r0,
    const float* __restrict__ Wq, const float* __restrict__ bq,
    const float* __restrict__ Wk, const float* __restrict__ bk,
    const float* __restrict__ Wv, const float* __restrict__ bv)
{
    const int tid = threadIdx.x;
    const int p = tid >> 6, c = tid & 63;
    const u64* xp = sX2 + p * 64;

    u64 aq = 0, ak = 0, av = 0;
#pragma unroll 8
    for (int i = 0; i < 64; i++) {
        u64 x2 = xp[i];
        fma2(aq, x2, splat(__ldg(Wq + i * 64 + c)));
        fma2(ak, x2, splat(__ldg(Wk + i * 64 + c)));
        fma2(av, x2, splat(__ldg(Wv + i * 64 + c)));
    }
    const float scl = 0.35355339059327373f;   // 1/sqrt(8)
    float bqc = __ldg(bq + c), bkc = __ldg(bk + c), bvc = __ldg(bv + c);
    float qx, qy, kx, ky, vx, vy;
    unpk(aq, qx, qy); unpk(ak, kx, ky); unpk(av, vx, vy);
    qx = (qx + bqc) * scl; qy = (qy + bqc) * scl;
    kx += bkc; ky += bkc;
    vx += bvc; vy += bvc;

    const int h = c >> 3, jj = c & 7;
#pragma unroll
    for (int rr = 0; rr < 2; rr++) {
        int r = r0 + 2 * p + rr;
        int b = r >> 9, s = r & 511;
        int base = ((b * NH + h) * SS + s) * 8 + jj;
        g_q[base]  = rr ? qy : qx;
        g_kk[base] = rr ? ky : kx;
        g_vv[base] = rr ? vy : vx;
    }
}

// ---------------------------------------------------------------------------
// First launch: y = ytmp = x; qkv(x).  grid 256, block 256 (8 rows/block).
__global__ void __launch_bounds__(256) q0_kernel(
    const float* __restrict__ x,
    const float* __restrict__ Wq, const float* __restrict__ bq,
    const float* __restrict__ Wk, const float* __restrict__ bk,
    const float* __restrict__ Wv, const float* __restrict__ bv)
{
    __shared__ u64 sX2[4 * 64];
    const int tid = threadIdx.x;
    const int p = tid >> 6, c = tid & 63;
    const int r0 = blockIdx.x * 8;
    {
        int i0 = (r0 + 2 * p) * 64 + c;
        float a = x[i0], b = x[i0 + 64];
        g_y[i0] = a;    g_y[i0 + 64] = b;
        g_ytmp[i0] = a; g_ytmp[i0 + 64] = b;
        sX2[p * 64 + c] = pk(a, b);
    }
    __syncthreads();
    qkv_phase(sX2, r0, Wq, bq, Wk, bk, Wv, bv);
}

// ---------------------------------------------------------------------------
// Attention: grid 256 = (bh 32) x (qtile 8 of 64 queries). Block 128 threads.
// Warp = 16 queries: lane&7 -> query-pair slot, lane>>3 -> key quarter.
// Each thread: 2 queries x 128 keys, dims packed in f32x2.
__global__ void __launch_bounds__(128) attn_kernel()
{
    __shared__ ulonglong2 ks[SS * 2];   // 16KB (K rows as 2x ulonglong2)
    __shared__ ulonglong2 vs[SS * 2];   // 16KB

    const int bh = blockIdx.x >> 3;
    const int qt = blockIdx.x & 7;
    const int tid = threadIdx.x;

    const ulonglong2* kg = (const ulonglong2*)g_kk + bh * SS * 2;
    const ulonglong2* vg = (const ulonglong2*)g_vv + bh * SS * 2;
    for (int i = tid; i < SS * 2; i += 128) { ks[i] = kg[i]; vs[i] = vg[i]; }
    __syncthreads();

    const int lane = tid & 31;
    const int warp = tid >> 5;
    const int quarter = lane >> 3;
    const int qg = qt * 64 + warp * 16 + (lane & 7) * 2;   // first of 2 queries

    // load both queries (dims packed: 4 u64 each)
    u64 q[2][4];
#pragma unroll
    for (int j = 0; j < 2; j++) {
        const ulonglong2* qp = (const ulonglong2*)g_q + (bh * SS + qg + j) * 2;
        ulonglong2 qa = qp[0], qb = qp[1];
        q[j][0] = qa.x; q[j][1] = qa.y; q[j][2] = qb.x; q[j][3] = qb.y;
    }

    float m[2] = {-1e30f, -1e30f}, l[2] = {0.f, 0.f};
    u64 o[2][4];
#pragma unroll
    for (int j = 0; j < 2; j++)
#pragma unroll
        for (int d = 0; d < 4; d++) o[j][d] = 0;

    const int t0 = quarter * 128;
#pragma unroll 2
    for (int i = 0; i < 128; i++) {
        const int t = t0 + i;
        ulonglong2 ka = ks[2 * t], kb = ks[2 * t + 1];
        float s[2];
#pragma unroll
        for (int j = 0; j < 2; j++) {
            u64 s2 = 0;
            fma2(s2, q[j][0], ka.x); fma2(s2, q[j][1], ka.y);
            fma2(s2, q[j][2], kb.x); fma2(s2, q[j][3], kb.y);
            float sx, sy; unpk(s2, sx, sy);
            s[j] = sx + sy;
        }
        ulonglong2 va = vs[2 * t], vb = vs[2 * t + 1];
#pragma unroll
        for (int j = 0; j < 2; j++) {
            if (s[j] > m[j]) {
                float corr = __expf(m[j] - s[j]);
                l[j] *= corr;
                u64 c2 = splat(corr);
#pragma unroll
                for (int d = 0; d < 4; d++) o[j][d] = mul2(o[j][d], c2);
                m[j] = s[j];
            }
            float pr = __expf(s[j] - m[j]);
            l[j] += pr;
            u64 p2 = splat(pr);
            fma2(o[j][0], p2, va.x); fma2(o[j][1], p2, va.y);
            fma2(o[j][2], p2, vb.x); fma2(o[j][3], p2, vb.y);
        }
    }

    // unpack accumulators, merge 4 key-quarters (lanes l, l^8, l^16, l^24)
    float of[2][8];
#pragma unroll
    for (int j = 0; j < 2; j++)
#pragma unroll
        for (int d = 0; d < 4; d++)
            unpk(o[j][d], of[j][2 * d], of[j][2 * d + 1]);

#pragma unroll
    for (int d = 8; d <= 16; d <<= 1) {
#pragma unroll
        for (int j = 0; j < 2; j++) {
            float m2 = __shfl_xor_sync(0xffffffffu, m[j], d);
            float l2 = __shfl_xor_sync(0xffffffffu, l[j], d);
            float M  = fmaxf(m[j], m2);
            float sA = __expf(m[j] - M);
            float sB = __expf(m2 - M);
            l[j] = l[j] * sA + l2 * sB;
#pragma unroll
            for (int e = 0; e < 8; e++) {
                float o2 = __shfl_xor_sync(0xffffffffu, of[j][e], d);
                of[j][e] = of[j][e] * sA + o2 * sB;
            }
            m[j] = M;
        }
    }

    if (quarter == 0) {
        const int b = bh >> 3, h = bh & 7;
#pragma unroll
        for (int j = 0; j < 2; j++) {
            float inv = 1.f / l[j];
            float* dst = g_att + ((b * SS + qg + j) * DD) + h * 8;
            *(float4*)(dst)     = make_float4(of[j][0]*inv, of[j][1]*inv,
                                              of[j][2]*inv, of[j][3]*inv);
            *(float4*)(dst + 4) = make_float4(of[j][4]*inv, of[j][5]*inv,
                                              of[j][6]*inv, of[j][7]*inv);
        }
    }
}

// ---------------------------------------------------------------------------
// Fused: out-proj + residual + FFN -> k[stage]; RK combo -> ytmp (or y);
// next-stage qkv.  Block 256 threads, 8 rows (4 row-pairs), thread (p, c).
// All activations row-pair packed in f32x2.
__global__ void __launch_bounds__(256) fused_kernel(
    const float* __restrict__ Wo, const float* __restrict__ bo,
    const float* __restrict__ W1, const float* __restrict__ b1,
    const float* __restrict__ W2, const float* __restrict__ b2,
    const float* __restrict__ Wq, const float* __restrict__ bq,
    const float* __restrict__ Wk, const float* __restrict__ bk,
    const float* __restrict__ Wv, const float* __restrict__ bv,
    StageCtl ctl)
{
    __shared__ u64 sA2[4 * 64];
    __shared__ u64 sH2[4 * 64];
    __shared__ u64 sU2[4 * 256];
    __shared__ u64 sX2[4 * 64];

    const int tid = threadIdx.x;
    const int p = tid >> 6, c = tid & 63;
    const int r0 = blockIdx.x * 8;
    const int rA = r0 + 2 * p;

    // load att rows (pair-packed)
    {
        int i0 = rA * 64 + c;
        sA2[p * 64 + c] = pk(g_att[i0], g_att[i0 + 64]);
    }
    __syncthreads();

    // ---- Phase B: out projection (Wo) + residual ----
    u64 o1;
    {
        u64 acc0 = 0, acc1 = 0;
        const u64* ap = sA2 + p * 64;
#pragma unroll 8
        for (int i = 0; i < 64; i += 2) {
            fma2(acc0, ap[i],     splat(__ldg(Wo + i * 64 + c)));
            fma2(acc1, ap[i + 1], splat(__ldg(Wo + (i + 1) * 64 + c)));
        }
        o1 = add2(add2(acc0, acc1), splat(__ldg(bo + c)));
        int i0 = rA * 64 + c;
        u64 yt = pk(g_ytmp[i0], g_ytmp[i0 + 64]);
        sH2[p * 64 + c] = add2(yt, o1);
    }
    __syncthreads();

    // ---- Phase C: hidden layer (W1) + relu; thread does 4 hidden cols ----
    {
        u64 u[4] = {0, 0, 0, 0};
        const u64* hp = sH2 + p * 64;
#pragma unroll 4
        for (int i = 0; i < 64; i++) {
            u64 h2 = hp[i];
            const float* wrow = W1 + i * 256 + c;
            fma2(u[0], h2, splat(__ldg(wrow)));
            fma2(u[1], h2, splat(__ldg(wrow + 64)));
            fma2(u[2], h2, splat(__ldg(wrow + 128)));
            fma2(u[3], h2, splat(__ldg(wrow + 192)));
        }
#pragma unroll
        for (int k = 0; k < 4; k++) {
            float b1c = __ldg(b1 + c + 64 * k);
            float ux, uy; unpk(u[k], ux, uy);
            sU2[p * 256 + c + 64 * k] = pk(fmaxf(ux + b1c, 0.f),
                                           fmaxf(uy + b1c, 0.f));
        }
    }
    __syncthreads();

    // ---- Phase D: second FFN layer (W2); k_stage = att_proj + ffn ----
    u64 kv2;
    {
        u64 acc0 = 0, acc1 = 0;
        const u64* up = sU2 + p * 256;
#pragma unroll 8
        for (int i = 0; i < 256; i += 2) {
            fma2(acc0, up[i],     splat(__ldg(W2 + i * 64 + c)));
            fma2(acc1, up[i + 1], splat(__ldg(W2 + (i + 1) * 64 + c)));
        }
        kv2 = add2(o1, add2(add2(acc0, acc1), splat(__ldg(b2 + c))));
        float kx, ky; unpk(kv2, kx, ky);
        float* dst = g_kst + (ctl.stage * NROWS + rA) * 64 + c;
        dst[0] = kx; dst[64] = ky;
    }

    // ---- Phase E: RK combination -> ytmp (and optionally y) ----
    {
        int i0 = rA * 64 + c;
        u64 v2 = pk(g_y[i0], g_y[i0 + 64]);
        for (int cc = 0; cc < ctl.nc; cc++) {
            u64 k2;
            if (cc == ctl.stage) k2 = kv2;
            else {
                const float* kp = g_kst + (cc * NROWS + rA) * 64 + c;
                k2 = pk(kp[0], kp[64]);
            }
            fma2(v2, k2, splat(ctl.ac[cc]));
        }
        float vx, vy; unpk(v2, vx, vy);
        if (ctl.write_y) { g_y[i0] = vx; g_y[i0 + 64] = vy; }
        g_ytmp[i0] = vx; g_ytmp[i0 + 64] = vy;
        sX2[p * 64 + c] = v2;
    }
    __syncthreads();

    // ---- Phase F: next-stage qkv ----
    if (ctl.do_qkv)
        qkv_phase(sX2, r0, Wq, bq, Wk, bk, Wv, bv);
}

// ---------------------------------------------------------------------------
extern "C" void kernel_launch(void* const* d_in, const int* in_sizes, int n_in,
                              void* d_out, int out_size)
{
    (void)in_sizes; (void)n_in; (void)out_size;

    const float* x  = (const float*)d_in[0];
    // d_in[1] = mask: broadcasts over key axis -> softmax-invariant; ignored.
    const float* Wq = (const float*)d_in[2];
    const float* bq = (const float*)d_in[3];
    const float* Wk = (const float*)d_in[4];
    const float* bk = (const float*)d_in[5];
    const float* Wv = (const float*)d_in[6];
    const float* bv = (const float*)d_in[7];
    const float* Wo = (const float*)d_in[8];
    const float* bo = (const float*)d_in[9];
    const float* W1 = (const float*)d_in[10];
    const float* b1 = (const float*)d_in[11];
    const float* W2 = (const float*)d_in[12];
    const float* b2 = (const float*)d_in[13];

    static const double acoef[6][5] = {
        {0, 0, 0, 0, 0},
        {0.25, 0, 0, 0, 0},
        {3.0/32.0, 9.0/32.0, 0, 0, 0},
        {1932.0/2197.0, -7200.0/2197.0, 7296.0/2197.0, 0, 0},
        {439.0/216.0, -8.0, 3680.0/513.0, -845.0/4104.0, 0},
        {-8.0/27.0, 2.0, -3544.0/2565.0, 1859.0/4104.0, -11.0/40.0},
    };
    static const double bcoef[6] = {
        16.0/135.0, 0.0, 6656.0/12825.0, 28561.0/56430.0, -9.0/50.0, 2.0/55.0
    };

    q0_kernel<<<256, 256>>>(x, Wq, bq, Wk, bk, Wv, bv);

    for (int step = 0; step < 4; step++) {
        for (int st = 0; st < 6; st++) {
            attn_kernel<<<256, 128>>>();
            StageCtl ctl;
            ctl.stage = st;
            if (st < 5) {
                ctl.nc = st + 1;
                for (int c = 0; c < 6; c++)
                    ctl.ac[c] = (c <= st)
                        ? (float)((double)DT_F * acoef[st + 1][c]) : 0.f;
                ctl.do_qkv  = 1;
                ctl.write_y = 0;
            } else {
                ctl.nc = 6;
                for (int c = 0; c < 6; c++)
                    ctl.ac[c] = (float)((double)DT_F * bcoef[c]);
                ctl.write_y = 1;
                ctl.do_qkv  = (step < 3) ? 1 : 0;
            }
            fused_kernel<<<256, 256>>>(Wo, bo, W1, b1, W2, b2,
                                       Wq, bq, Wk, bk, Wv, bv, ctl);
        }
    }

    copy_out_kernel<<<128, 256>>>((float*)d_out);
}

// round 5
// speedup vs baseline: 1.0032x; 1.0032x over previous
#include <cuda_runtime.h>

typedef unsigned long long u64;

#define NB   4
#define SS   512
#define DD   64
#define NH   8
#define NROWS (NB*SS)      // 2048
#define DT_F 0.25f

// Persistent device scratch (no allocations allowed)
__device__ __align__(16) float g_y[NROWS*DD];
__device__ __align__(16) float g_ytmp[NROWS*DD];
__device__ __align__(16) float g_kst[6*NROWS*DD];
__device__ __align__(16) float g_q[NROWS*DD];
__device__ __align__(16) float g_kk[NROWS*DD];
__device__ __align__(16) float g_vv[NROWS*DD];
__device__ __align__(16) float g_att[NROWS*DD];

struct StageCtl {
    float ac[6];
    int   nc;
    int   stage;
    int   do_qkv;
    int   write_y;
};

// ---------------- f32x2 helpers (packed fp32, sm_100a) ----------------
__device__ __forceinline__ u64 pk(float x, float y) {
    u64 r; asm("mov.b64 %0,{%1,%2};" : "=l"(r) : "f"(x), "f"(y)); return r;
}
__device__ __forceinline__ void unpk(u64 v, float& x, float& y) {
    asm("mov.b64 {%0,%1},%2;" : "=f"(x), "=f"(y) : "l"(v));
}
__device__ __forceinline__ u64 splat(float x) {
    u64 r; asm("mov.b64 %0,{%1,%1};" : "=l"(r) : "f"(x)); return r;
}
__device__ __forceinline__ void fma2(u64& d, u64 a, u64 b) {
    asm("fma.rn.f32x2 %0,%1,%2,%0;" : "+l"(d) : "l"(a), "l"(b));
}
__device__ __forceinline__ u64 add2(u64 a, u64 b) {
    u64 d; asm("add.rn.f32x2 %0,%1,%2;" : "=l"(d) : "l"(a), "l"(b)); return d;
}
__device__ __forceinline__ u64 mul2(u64 a, u64 b) {
    u64 d; asm("mul.rn.f32x2 %0,%1,%2;" : "=l"(d) : "l"(a), "l"(b)); return d;
}

// ---------------------------------------------------------------------------
__global__ void __launch_bounds__(256) copy_out_kernel(float* __restrict__ out) {
    int i = blockIdx.x * blockDim.x + threadIdx.x;
    ((float4*)out)[i] = ((const float4*)g_y)[i];
}

// ---------------------------------------------------------------------------
// qkv GEMV over row-pair-packed activations sX2 ([4 pairs][64] u64).
// Thread (p = tid>>6, c = tid&63): q,k,v column c of rows {2p, 2p+1}.
__device__ __forceinline__ void qkv_phase(
    const u64* sX2, int r0,
    const float* __restrict__ Wq, const float* __restrict__ bq,
    const float* __restrict__ Wk, const float* __restrict__ bk,
    const float* __restrict__ Wv, const float* __restrict__ bv)
{
    const int tid = threadIdx.x;
    const int p = tid >> 6, c = tid & 63;
    const u64* xp = sX2 + p * 64;

    u64 aq = 0, ak = 0, av = 0;
#pragma unroll 8
    for (int i = 0; i < 64; i++) {
        u64 x2 = xp[i];
        fma2(aq, x2, splat(__ldg(Wq + i * 64 + c)));
        fma2(ak, x2, splat(__ldg(Wk + i * 64 + c)));
        fma2(av, x2, splat(__ldg(Wv + i * 64 + c)));
    }
    const float scl = 0.35355339059327373f;   // 1/sqrt(8)
    float bqc = __ldg(bq + c), bkc = __ldg(bk + c), bvc = __ldg(bv + c);
    float qx, qy, kx, ky, vx, vy;
    unpk(aq, qx, qy); unpk(ak, kx, ky); unpk(av, vx, vy);
    qx = (qx + bqc) * scl; qy = (qy + bqc) * scl;
    kx += bkc; ky += bkc;
    vx += bvc; vy += bvc;

    const int h = c >> 3, jj = c & 7;
#pragma unroll
    for (int rr = 0; rr < 2; rr++) {
        int r = r0 + 2 * p + rr;
        int b = r >> 9, s = r & 511;
        int base = ((b * NH + h) * SS + s) * 8 + jj;
        g_q[base]  = rr ? qy : qx;
        g_kk[base] = rr ? ky : kx;
        g_vv[base] = rr ? vy : vx;
    }
}

// ---------------------------------------------------------------------------
// First launch: y = ytmp = x; qkv(x).  grid 256, block 256 (8 rows/block).
__global__ void __launch_bounds__(256) q0_kernel(
    const float* __restrict__ x,
    const float* __restrict__ Wq, const float* __restrict__ bq,
    const float* __restrict__ Wk, const float* __restrict__ bk,
    const float* __restrict__ Wv, const float* __restrict__ bv)
{
    __shared__ u64 sX2[4 * 64];
    const int tid = threadIdx.x;
    const int p = tid >> 6, c = tid & 63;
    const int r0 = blockIdx.x * 8;
    {
        int i0 = (r0 + 2 * p) * 64 + c;
        float a = x[i0], b = x[i0 + 64];
        g_y[i0] = a;    g_y[i0 + 64] = b;
        g_ytmp[i0] = a; g_ytmp[i0 + 64] = b;
        sX2[p * 64 + c] = pk(a, b);
    }
    __syncthreads();
    qkv_phase(sX2, r0, Wq, bq, Wk, bk, Wv, bv);
}

// ---------------------------------------------------------------------------
// Attention: grid 256 = (bh 32) x (qtile 8 of 64 queries). Block 128 threads.
// Warp = 16 queries: lane&7 -> query-pair slot, lane>>3 -> key quarter.
// Each thread: 2 queries x 128 keys, dims packed in f32x2.
__global__ void __launch_bounds__(128) attn_kernel()
{
    __shared__ ulonglong2 ks[SS * 2];   // 16KB (K rows as 2x ulonglong2)
    __shared__ ulonglong2 vs[SS * 2];   // 16KB

    const int bh = blockIdx.x >> 3;
    const int qt = blockIdx.x & 7;
    const int tid = threadIdx.x;

    const ulonglong2* kg = (const ulonglong2*)g_kk + bh * SS * 2;
    const ulonglong2* vg = (const ulonglong2*)g_vv + bh * SS * 2;
    for (int i = tid; i < SS * 2; i += 128) { ks[i] = kg[i]; vs[i] = vg[i]; }
    __syncthreads();

    const int lane = tid & 31;
    const int warp = tid >> 5;
    const int quarter = lane >> 3;
    const int qg = qt * 64 + warp * 16 + (lane & 7) * 2;   // first of 2 queries

    // load both queries (dims packed: 4 u64 each)
    u64 q[2][4];
#pragma unroll
    for (int j = 0; j < 2; j++) {
        const ulonglong2* qp = (const ulonglong2*)g_q + (bh * SS + qg + j) * 2;
        ulonglong2 qa = qp[0], qb = qp[1];
        q[j][0] = qa.x; q[j][1] = qa.y; q[j][2] = qb.x; q[j][3] = qb.y;
    }

    float m[2] = {-1e30f, -1e30f}, l[2] = {0.f, 0.f};
    u64 o[2][4];
#pragma unroll
    for (int j = 0; j < 2; j++)
#pragma unroll
        for (int d = 0; d < 4; d++) o[j][d] = 0;

    const int t0 = quarter * 128;
#pragma unroll 2
    for (int i = 0; i < 128; i++) {
        const int t = t0 + i;
        ulonglong2 ka = ks[2 * t], kb = ks[2 * t + 1];
        float s[2];
#pragma unroll
        for (int j = 0; j < 2; j++) {
            u64 s2 = 0;
            fma2(s2, q[j][0], ka.x); fma2(s2, q[j][1], ka.y);
            fma2(s2, q[j][2], kb.x); fma2(s2, q[j][3], kb.y);
            float sx, sy; unpk(s2, sx, sy);
            s[j] = sx + sy;
        }
        ulonglong2 va = vs[2 * t], vb = vs[2 * t + 1];
#pragma unroll
        for (int j = 0; j < 2; j++) {
            if (s[j] > m[j]) {
                float corr = __expf(m[j] - s[j]);
                l[j] *= corr;
                u64 c2 = splat(corr);
#pragma unroll
                for (int d = 0; d < 4; d++) o[j][d] = mul2(o[j][d], c2);
                m[j] = s[j];
            }
            float pr = __expf(s[j] - m[j]);
            l[j] += pr;
            u64 p2 = splat(pr);
            fma2(o[j][0], p2, va.x); fma2(o[j][1], p2, va.y);
            fma2(o[j][2], p2, vb.x); fma2(o[j][3], p2, vb.y);
        }
    }

    // unpack accumulators, merge 4 key-quarters (lanes l, l^8, l^16, l^24)
    float of[2][8];
#pragma unroll
    for (int j = 0; j < 2; j++)
#pragma unroll
        for (int d = 0; d < 4; d++)
            unpk(o[j][d], of[j][2 * d], of[j][2 * d + 1]);

#pragma unroll
    for (int d = 8; d <= 16; d <<= 1) {
#pragma unroll
        for (int j = 0; j < 2; j++) {
            float m2 = __shfl_xor_sync(0xffffffffu, m[j], d);
            float l2 = __shfl_xor_sync(0xffffffffu, l[j], d);
            float M  = fmaxf(m[j], m2);
            float sA = __expf(m[j] - M);
            float sB = __expf(m2 - M);
            l[j] = l[j] * sA + l2 * sB;
#pragma unroll
            for (int e = 0; e < 8; e++) {
                float o2 = __shfl_xor_sync(0xffffffffu, of[j][e], d);
                of[j][e] = of[j][e] * sA + o2 * sB;
            }
            m[j] = M;
        }
    }

    if (quarter == 0) {
        const int b = bh >> 3, h = bh & 7;
#pragma unroll
        for (int j = 0; j < 2; j++) {
            float inv = 1.f / l[j];
            float* dst = g_att + ((b * SS + qg + j) * DD) + h * 8;
            *(float4*)(dst)     = make_float4(of[j][0]*inv, of[j][1]*inv,
                                              of[j][2]*inv, of[j][3]*inv);
            *(float4*)(dst + 4) = make_float4(of[j][4]*inv, of[j][5]*inv,
                                              of[j][6]*inv, of[j][7]*inv);
        }
    }
}

// ---------------------------------------------------------------------------
// Fused: out-proj + residual + FFN -> k[stage]; RK combo -> ytmp (or y);
// next-stage qkv.  Block 256 threads, 8 rows (4 row-pairs), thread (p, c).
// All activations row-pair packed in f32x2.
__global__ void __launch_bounds__(256) fused_kernel(
    const float* __restrict__ Wo, const float* __restrict__ bo,
    const float* __restrict__ W1, const float* __restrict__ b1,
    const float* __restrict__ W2, const float* __restrict__ b2,
    const float* __restrict__ Wq, const float* __restrict__ bq,
    const float* __restrict__ Wk, const float* __restrict__ bk,
    const float* __restrict__ Wv, const float* __restrict__ bv,
    StageCtl ctl)
{
    __shared__ u64 sA2[4 * 64];
    __shared__ u64 sH2[4 * 64];
    __shared__ u64 sU2[4 * 256];
    __shared__ u64 sX2[4 * 64];

    const int tid = threadIdx.x;
    const int p = tid >> 6, c = tid & 63;
    const int r0 = blockIdx.x * 8;
    const int rA = r0 + 2 * p;

    // load att rows (pair-packed)
    {
        int i0 = rA * 64 + c;
        sA2[p * 64 + c] = pk(g_att[i0], g_att[i0 + 64]);
    }
    __syncthreads();

    // ---- Phase B: out projection (Wo) + residual ----
    u64 o1;
    {
        u64 acc0 = 0, acc1 = 0;
        const u64* ap = sA2 + p * 64;
#pragma unroll 8
        for (int i = 0; i < 64; i += 2) {
            fma2(acc0, ap[i],     splat(__ldg(Wo + i * 64 + c)));
            fma2(acc1, ap[i + 1], splat(__ldg(Wo + (i + 1) * 64 + c)));
        }
        o1 = add2(add2(acc0, acc1), splat(__ldg(bo + c)));
        int i0 = rA * 64 + c;
        u64 yt = pk(g_ytmp[i0], g_ytmp[i0 + 64]);
        sH2[p * 64 + c] = add2(yt, o1);
    }
    __syncthreads();

    // ---- Phase C: hidden layer (W1) + relu; thread does 4 hidden cols ----
    {
        u64 u[4] = {0, 0, 0, 0};
        const u64* hp = sH2 + p * 64;
#pragma unroll 4
        for (int i = 0; i < 64; i++) {
            u64 h2 = hp[i];
            const float* wrow = W1 + i * 256 + c;
            fma2(u[0], h2, splat(__ldg(wrow)));
            fma2(u[1], h2, splat(__ldg(wrow + 64)));
            fma2(u[2], h2, splat(__ldg(wrow + 128)));
            fma2(u[3], h2, splat(__ldg(wrow + 192)));
        }
#pragma unroll
        for (int k = 0; k < 4; k++) {
            float b1c = __ldg(b1 + c + 64 * k);
            float ux, uy; unpk(u[k], ux, uy);
            sU2[p * 256 + c + 64 * k] = pk(fmaxf(ux + b1c, 0.f),
                                           fmaxf(uy + b1c, 0.f));
        }
    }
    __syncthreads();

    // ---- Phase D: second FFN layer (W2); k_stage = att_proj + ffn ----
    u64 kv2;
    {
        u64 acc0 = 0, acc1 = 0;
        const u64* up = sU2 + p * 256;
#pragma unroll 8
        for (int i = 0; i < 256; i += 2) {
            fma2(acc0, up[i],     splat(__ldg(W2 + i * 64 + c)));
            fma2(acc1, up[i + 1], splat(__ldg(W2 + (i + 1) * 64 + c)));
        }
        kv2 = add2(o1, add2(add2(acc0, acc1), splat(__ldg(b2 + c))));
        float kx, ky; unpk(kv2, kx, ky);
        float* dst = g_kst + (ctl.stage * NROWS + rA) * 64 + c;
        dst[0] = kx; dst[64] = ky;
    }

    // ---- Phase E: RK combination -> ytmp (and optionally y) ----
    {
        int i0 = rA * 64 + c;
        u64 v2 = pk(g_y[i0], g_y[i0 + 64]);
        for (int cc = 0; cc < ctl.nc; cc++) {
            u64 k2;
            if (cc == ctl.stage) k2 = kv2;
            else {
                const float* kp = g_kst + (cc * NROWS + rA) * 64 + c;
                k2 = pk(kp[0], kp[64]);
            }
            fma2(v2, k2, splat(ctl.ac[cc]));
        }
        float vx, vy; unpk(v2, vx, vy);
        if (ctl.write_y) { g_y[i0] = vx; g_y[i0 + 64] = vy; }
        g_ytmp[i0] = vx; g_ytmp[i0 + 64] = vy;
        sX2[p * 64 + c] = v2;
    }
    __syncthreads();

    // ---- Phase F: next-stage qkv ----
    if (ctl.do_qkv)
        qkv_phase(sX2, r0, Wq, bq, Wk, bk, Wv, bv);
}

// ---------------------------------------------------------------------------
extern "C" void kernel_launch(void* const* d_in, const int* in_sizes, int n_in,
                              void* d_out, int out_size)
{
    (void)in_sizes; (void)n_in; (void)out_size;

    const float* x  = (const float*)d_in[0];
    // d_in[1] = mask: broadcasts over key axis -> softmax-invariant; ignored.
    const float* Wq = (const float*)d_in[2];
    const float* bq = (const float*)d_in[3];
    const float* Wk = (const float*)d_in[4];
    const float* bk = (const float*)d_in[5];
    const float* Wv = (const float*)d_in[6];
    const float* bv = (const float*)d_in[7];
    const float* Wo = (const float*)d_in[8];
    const float* bo = (const float*)d_in[9];
    const float* W1 = (const float*)d_in[10];
    const float* b1 = (const float*)d_in[11];
    const float* W2 = (const float*)d_in[12];
    const float* b2 = (const float*)d_in[13];

    static const double acoef[6][5] = {
        {0, 0, 0, 0, 0},
        {0.25, 0, 0, 0, 0},
        {3.0/32.0, 9.0/32.0, 0, 0, 0},
        {1932.0/2197.0, -7200.0/2197.0, 7296.0/2197.0, 0, 0},
        {439.0/216.0, -8.0, 3680.0/513.0, -845.0/4104.0, 0},
        {-8.0/27.0, 2.0, -3544.0/2565.0, 1859.0/4104.0, -11.0/40.0},
    };
    static const double bcoef[6] = {
        16.0/135.0, 0.0, 6656.0/12825.0, 28561.0/56430.0, -9.0/50.0, 2.0/55.0
    };

    q0_kernel<<<256, 256>>>(x, Wq, bq, Wk, bk, Wv, bv);

    for (int step = 0; step < 4; step++) {
        for (int st = 0; st < 6; st++) {
            attn_kernel<<<256, 128>>>();
            StageCtl ctl;
            ctl.stage = st;
            if (st < 5) {
                ctl.nc = st + 1;
                for (int c = 0; c < 6; c++)
                    ctl.ac[c] = (c <= st)
                        ? (float)((double)DT_F * acoef[st + 1][c]) : 0.f;
                ctl.do_qkv  = 1;
                ctl.write_y = 0;
            } else {
                ctl.nc = 6;
                for (int c = 0; c < 6; c++)
                    ctl.ac[c] = (float)((double)DT_F * bcoef[c]);
                ctl.write_y = 1;
                ctl.do_qkv  = (step < 3) ? 1 : 0;
            }
            fused_kernel<<<256, 256>>>(Wo, bo, W1, b1, W2, b2,
                                       Wq, bq, Wk, bk, Wv, bv, ctl);
        }
    }

    copy_out_kernel<<<128, 256>>>((float*)d_out);
}

// round 6
// speedup vs baseline: 1.3885x; 1.3842x over previous
#include <cuda_runtime.h>

typedef unsigned long long u64;

#define NB   4
#define SS   512
#define DD   64
#define NH   8
#define NROWS (NB*SS)      // 2048
#define DT_F 0.25f
#define PSTR 12            // floats per attention partial record

// Persistent device scratch (no allocations allowed)
__device__ __align__(16) float g_y[NROWS*DD];
__device__ __align__(16) float g_ytmp[NROWS*DD];
__device__ __align__(16) float g_kst[6*NROWS*DD];
__device__ __align__(16) float g_q[NROWS*DD];
__device__ __align__(16) float g_kk[NROWS*DD];
__device__ __align__(16) float g_vv[NROWS*DD];
// attention partials: [bh][s][half][{o0..o7, m, l, pad, pad}]
__device__ __align__(16) float g_attp[32*SS*2*PSTR];

struct StageCtl {
    float ac[6];
    int   nc;
    int   stage;
    int   do_qkv;
    int   write_y;
};

// ---------------- f32x2 helpers ----------------
__device__ __forceinline__ u64 pk(float x, float y) {
    u64 r; asm("mov.b64 %0,{%1,%2};" : "=l"(r) : "f"(x), "f"(y)); return r;
}
__device__ __forceinline__ void unpk(u64 v, float& x, float& y) {
    asm("mov.b64 {%0,%1},%2;" : "=f"(x), "=f"(y) : "l"(v));
}
__device__ __forceinline__ u64 splat(float x) {
    u64 r; asm("mov.b64 %0,{%1,%1};" : "=l"(r) : "f"(x)); return r;
}
__device__ __forceinline__ void fma2(u64& d, u64 a, u64 b) {
    asm("fma.rn.f32x2 %0,%1,%2,%0;" : "+l"(d) : "l"(a), "l"(b));
}
__device__ __forceinline__ u64 add2(u64 a, u64 b) {
    u64 d; asm("add.rn.f32x2 %0,%1,%2;" : "=l"(d) : "l"(a), "l"(b)); return d;
}
__device__ __forceinline__ float elem(u64 v, int h) {
    float x, y; unpk(v, x, y); return h ? y : x;
}

// ---------------------------------------------------------------------------
__global__ void __launch_bounds__(256) copy_out_kernel(float* __restrict__ out) {
    int i = blockIdx.x * blockDim.x + threadIdx.x;
    ((float4*)out)[i] = ((const float4*)g_y)[i];
}

// ---------------------------------------------------------------------------
// qkv GEMV for q0 only: row-pair packed activations sX2 ([4 pairs][64]).
__device__ __forceinline__ void qkv_phase_q0(
    const u64* sX2, int r0,
    const float* __restrict__ Wq, const float* __restrict__ bq,
    const float* __restrict__ Wk, const float* __restrict__ bk,
    const float* __restrict__ Wv, const float* __restrict__ bv)
{
    const int tid = threadIdx.x;
    const int p = tid >> 6, c = tid & 63;
    const u64* xp = sX2 + p * 64;

    u64 aq = 0, ak = 0, av = 0;
#pragma unroll 8
    for (int i = 0; i < 64; i++) {
        u64 x2 = xp[i];
        fma2(aq, x2, splat(__ldg(Wq + i * 64 + c)));
        fma2(ak, x2, splat(__ldg(Wk + i * 64 + c)));
        fma2(av, x2, splat(__ldg(Wv + i * 64 + c)));
    }
    const float scl = 0.35355339059327373f;
    float bqc = __ldg(bq + c), bkc = __ldg(bk + c), bvc = __ldg(bv + c);
    float qx, qy, kx, ky, vx, vy;
    unpk(aq, qx, qy); unpk(ak, kx, ky); unpk(av, vx, vy);
    qx = (qx + bqc) * scl; qy = (qy + bqc) * scl;
    kx += bkc; ky += bkc; vx += bvc; vy += bvc;

    const int h = c >> 3, jj = c & 7;
#pragma unroll
    for (int rr = 0; rr < 2; rr++) {
        int r = r0 + 2 * p + rr;
        int b = r >> 9, s = r & 511;
        int base = ((b * NH + h) * SS + s) * 8 + jj;
        g_q[base]  = rr ? qy : qx;
        g_kk[base] = rr ? ky : kx;
        g_vv[base] = rr ? vy : vx;
    }
}

__global__ void __launch_bounds__(256) q0_kernel(
    const float* __restrict__ x,
    const float* __restrict__ Wq, const float* __restrict__ bq,
    const float* __restrict__ Wk, const float* __restrict__ bk,
    const float* __restrict__ Wv, const float* __restrict__ bv)
{
    __shared__ u64 sX2[4 * 64];
    const int tid = threadIdx.x;
    const int p = tid >> 6, c = tid & 63;
    const int r0 = blockIdx.x * 8;
    {
        int i0 = (r0 + 2 * p) * 64 + c;
        float a = x[i0], b = x[i0 + 64];
        g_y[i0] = a;    g_y[i0 + 64] = b;
        g_ytmp[i0] = a; g_ytmp[i0 + 64] = b;
        sX2[p * 64 + c] = pk(a, b);
    }
    __syncthreads();
    qkv_phase_q0(sX2, r0, Wq, bq, Wk, bk, Wv, bv);
}

// ---------------------------------------------------------------------------
// Attention with key-halving across blocks.
// grid 512 = bh(32) x qtile(8) x half(2); block 256.
// Block handles 64 queries x 256 keys; 4 threads/query (key quarters).
// Emits unnormalized partial {o[8], m, l} to g_attp.
__global__ void __launch_bounds__(256) attn_kernel()
{
    __shared__ float4 ks[256 * 2];   // 8KB
    __shared__ float4 vs[256 * 2];   // 8KB

    const int blk = blockIdx.x;
    const int half = blk & 1;
    const int qt  = (blk >> 1) & 7;
    const int bh  = blk >> 4;
    const int tid = threadIdx.x;

    const float4* kg = (const float4*)g_kk + (bh * SS + half * 256) * 2;
    const float4* vg = (const float4*)g_vv + (bh * SS + half * 256) * 2;
    for (int i = tid; i < 256 * 2; i += 256) { ks[i] = kg[i]; vs[i] = vg[i]; }
    __syncthreads();

    const int lane = tid & 31;
    const int warp = tid >> 5;
    const int quarter = lane >> 3;
    const int qg = qt * 64 + warp * 8 + (lane & 7);

    const float4* qp = (const float4*)g_q + (bh * SS + qg) * 2;
    const float4 q0 = qp[0];
    const float4 q1 = qp[1];

    float m = -1e30f, l = 0.f;
    float o[8];
#pragma unroll
    for (int j = 0; j < 8; j++) o[j] = 0.f;

    const int t0 = quarter * 64;
#pragma unroll 2
    for (int i = 0; i < 64; i++) {
        const int t = t0 + i;
        float4 ka = ks[2 * t], kb = ks[2 * t + 1];
        float s = q0.x * ka.x + q0.y * ka.y + q0.z * ka.z + q0.w * ka.w
                + q1.x * kb.x + q1.y * kb.y + q1.z * kb.z + q1.w * kb.w;
        if (s > m) {
            float corr = __expf(m - s);
            l *= corr;
#pragma unroll
            for (int j = 0; j < 8; j++) o[j] *= corr;
            m = s;
        }
        float p = __expf(s - m);
        l += p;
        float4 va = vs[2 * t], vb = vs[2 * t + 1];
        o[0] += p * va.x; o[1] += p * va.y; o[2] += p * va.z; o[3] += p * va.w;
        o[4] += p * vb.x; o[5] += p * vb.y; o[6] += p * vb.z; o[7] += p * vb.w;
    }

    // merge 4 key-quarters (lanes l, l^8, l^16, l^24 share a query)
#pragma unroll
    for (int d = 8; d <= 16; d <<= 1) {
        float m2 = __shfl_xor_sync(0xffffffffu, m, d);
        float l2 = __shfl_xor_sync(0xffffffffu, l, d);
        float M  = fmaxf(m, m2);
        float sA = __expf(m - M);
        float sB = __expf(m2 - M);
        l = l * sA + l2 * sB;
#pragma unroll
        for (int j = 0; j < 8; j++) {
            float o2 = __shfl_xor_sync(0xffffffffu, o[j], d);
            o[j] = o[j] * sA + o2 * sB;
        }
        m = M;
    }

    if (quarter == 0) {
        float* dst = g_attp + ((bh * SS + qg) * 2 + half) * PSTR;
        *(float4*)(dst)     = make_float4(o[0], o[1], o[2], o[3]);
        *(float4*)(dst + 4) = make_float4(o[4], o[5], o[6], o[7]);
        *(float4*)(dst + 8) = make_float4(m, l, 0.f, 0.f);
    }
}

// ---------------------------------------------------------------------------
// Fused: merge attn partials -> att; out-proj + residual + FFN -> k[stage];
// RK combo -> ytmp (or y); next-stage qkv.
// grid 512, block 256, 4 rows/block. Thread = (h2 = dot-half, p = row-pair, c).
// Activations stored as [i][4 rows] floats; pair reads = broadcast LDS.64.
__global__ void __launch_bounds__(256) fused_kernel(
    const float* __restrict__ Wo, const float* __restrict__ bo,
    const float* __restrict__ W1, const float* __restrict__ b1,
    const float* __restrict__ W2, const float* __restrict__ b2,
    const float* __restrict__ Wq, const float* __restrict__ bq,
    const float* __restrict__ Wk, const float* __restrict__ bk,
    const float* __restrict__ Wv, const float* __restrict__ bv,
    StageCtl ctl)
{
    __shared__ float sAf[64 * 4];     // att  [i][row]
    __shared__ float sHf[64 * 4];     // h    [i][row]
    __shared__ float sUf[256 * 4];    // relu [i][row]
    __shared__ float sXf[64 * 4];     // combined state [i][row]
    __shared__ u64 sPB[2 * 128];      // dot-half partials (B/D reuse)
    __shared__ u64 sPC[2 * 512];      // C partials; F reuses as 3x[2][128]

    const int tid = threadIdx.x;
    const int h2 = tid >> 7;          // dot-half
    const int p  = (tid >> 6) & 1;    // row-pair within block
    const int c  = tid & 63;
    const int r0 = blockIdx.x * 4;
    const int rA = r0 + 2 * p;        // pair's first row
    const int rME = rA + h2;          // row this thread owns for scalar phases

    // ---- Phase A: merge attention halves -> att value for row rME, col c ----
    {
        const int h = c >> 3, jj = c & 7;
        const int b = rME >> 9, s = rME & 511;
        const float* pp = g_attp + (((b * NH + h) * SS + s) * 2) * PSTR;
        float o0 = pp[jj], m0 = pp[8], l0 = pp[9];
        float o1 = pp[PSTR + jj], m1 = pp[PSTR + 8], l1 = pp[PSTR + 9];
        float M = fmaxf(m0, m1);
        float w0 = __expf(m0 - M), w1 = __expf(m1 - M);
        float att = (w0 * o0 + w1 * o1) / (w0 * l0 + w1 * l1);
        sAf[c * 4 + 2 * p + h2] = att;
    }
    __syncthreads();

    // ---- Phase B: out projection (Wo) ----
    u64 o1v;
    {
        u64 acc = 0;
        const int i0 = 32 * h2;
        const float2* ap = (const float2*)sAf;
#pragma unroll 8
        for (int i = i0; i < i0 + 32; i++) {
            float2 a2 = ap[i * 2 + p];
            fma2(acc, pk(a2.x, a2.y), splat(__ldg(Wo + i * 64 + c)));
        }
        sPB[h2 * 128 + p * 64 + c] = acc;
    }
    __syncthreads();
    {
        o1v = add2(add2(sPB[p * 64 + c], sPB[128 + p * 64 + c]),
                   splat(__ldg(bo + c)));
        // residual for row rME
        float hv = g_ytmp[rME * 64 + c] + elem(o1v, h2);
        sHf[c * 4 + 2 * p + h2] = hv;
    }
    __syncthreads();

    // ---- Phase C: hidden layer (W1) + relu ----
    {
        u64 u[4] = {0, 0, 0, 0};
        const int i0 = 32 * h2;
        const float2* hp = (const float2*)sHf;
#pragma unroll 4
        for (int i = i0; i < i0 + 32; i++) {
            float2 h2v = hp[i * 2 + p];
            u64 hx = pk(h2v.x, h2v.y);
            const float* wrow = W1 + i * 256 + c;
            fma2(u[0], hx, splat(__ldg(wrow)));
            fma2(u[1], hx, splat(__ldg(wrow + 64)));
            fma2(u[2], hx, splat(__ldg(wrow + 128)));
            fma2(u[3], hx, splat(__ldg(wrow + 192)));
        }
#pragma unroll
        for (int k = 0; k < 4; k++)
            sPC[(h2 * 2 + p) * 256 + c + 64 * k] = u[k];
    }
    __syncthreads();
    {
#pragma unroll
        for (int k = 0; k < 4; k++) {
            int col = c + 64 * k;
            u64 s2 = add2(sPC[p * 256 + col], sPC[512 + p * 256 + col]);
            float b1c = __ldg(b1 + col);
            sUf[col * 4 + 2 * p + h2] = fmaxf(elem(s2, h2) + b1c, 0.f);
        }
    }
    __syncthreads();

    // ---- Phase D: second FFN layer (W2) ----
    u64 kv2;
    {
        u64 acc0 = 0, acc1 = 0;
        const int i0 = 128 * h2;
        const float2* up = (const float2*)sUf;
#pragma unroll 8
        for (int i = i0; i < i0 + 128; i += 2) {
            float2 ua = up[i * 2 + p];
            float2 ub = up[(i + 1) * 2 + p];
            fma2(acc0, pk(ua.x, ua.y), splat(__ldg(W2 + i * 64 + c)));
            fma2(acc1, pk(ub.x, ub.y), splat(__ldg(W2 + (i + 1) * 64 + c)));
        }
        sPB[h2 * 128 + p * 64 + c] = add2(acc0, acc1);
    }
    __syncthreads();
    {
        u64 f2 = add2(sPB[p * 64 + c], sPB[128 + p * 64 + c]);
        kv2 = add2(o1v, add2(f2, splat(__ldg(b2 + c))));
        g_kst[(ctl.stage * NROWS + rME) * 64 + c] = elem(kv2, h2);
    }

    // ---- Phase E: RK combination (scalar, row rME) ----
    {
        float v = g_y[rME * 64 + c];
        float kme = elem(kv2, h2);
        for (int cc = 0; cc < ctl.nc; cc++) {
            float kx = (cc == ctl.stage) ? kme
                     : g_kst[(cc * NROWS + rME) * 64 + c];
            v = fmaf(ctl.ac[cc], kx, v);
        }
        if (ctl.write_y) g_y[rME * 64 + c] = v;
        g_ytmp[rME * 64 + c] = v;
        sXf[c * 4 + 2 * p + h2] = v;
    }
    __syncthreads();

    // ---- Phase F: next-stage qkv ----
    if (ctl.do_qkv) {
        u64 aq = 0, ak = 0, av = 0;
        const int i0 = 32 * h2;
        const float2* xp = (const float2*)sXf;
#pragma unroll 8
        for (int i = i0; i < i0 + 32; i++) {
            float2 x2 = xp[i * 2 + p];
            u64 xx = pk(x2.x, x2.y);
            fma2(aq, xx, splat(__ldg(Wq + i * 64 + c)));
            fma2(ak, xx, splat(__ldg(Wk + i * 64 + c)));
            fma2(av, xx, splat(__ldg(Wv + i * 64 + c)));
        }
        u64* sQ = sPC;          // [2][128]
        u64* sK = sPC + 256;    // [2][128]
        u64* sV = sPC + 512;    // [2][128]
        sQ[h2 * 128 + p * 64 + c] = aq;
        sK[h2 * 128 + p * 64 + c] = ak;
        sV[h2 * 128 + p * 64 + c] = av;
        __syncthreads();

        const float scl = 0.35355339059327373f;
        float qv = (elem(add2(sQ[p * 64 + c], sQ[128 + p * 64 + c]), h2)
                    + __ldg(bq + c)) * scl;
        float kv = elem(add2(sK[p * 64 + c], sK[128 + p * 64 + c]), h2)
                    + __ldg(bk + c);
        float vv = elem(add2(sV[p * 64 + c], sV[128 + p * 64 + c]), h2)
                    + __ldg(bv + c);

        const int h = c >> 3, jj = c & 7;
        const int b = rME >> 9, s = rME & 511;
        int base = ((b * NH + h) * SS + s) * 8 + jj;
        g_q[base]  = qv;
        g_kk[base] = kv;
        g_vv[base] = vv;
    }
}

// ---------------------------------------------------------------------------
extern "C" void kernel_launch(void* const* d_in, const int* in_sizes, int n_in,
                              void* d_out, int out_size)
{
    (void)in_sizes; (void)n_in; (void)out_size;

    const float* x  = (const float*)d_in[0];
    // d_in[1] = mask: broadcasts over key axis -> softmax-invariant; ignored.
    const float* Wq = (const float*)d_in[2];
    const float* bq = (const float*)d_in[3];
    const float* Wk = (const float*)d_in[4];
    const float* bk = (const float*)d_in[5];
    const float* Wv = (const float*)d_in[6];
    const float* bv = (const float*)d_in[7];
    const float* Wo = (const float*)d_in[8];
    const float* bo = (const float*)d_in[9];
    const float* W1 = (const float*)d_in[10];
    const float* b1 = (const float*)d_in[11];
    const float* W2 = (const float*)d_in[12];
    const float* b2 = (const float*)d_in[13];

    static const double acoef[6][5] = {
        {0, 0, 0, 0, 0},
        {0.25, 0, 0, 0, 0},
        {3.0/32.0, 9.0/32.0, 0, 0, 0},
        {1932.0/2197.0, -7200.0/2197.0, 7296.0/2197.0, 0, 0},
        {439.0/216.0, -8.0, 3680.0/513.0, -845.0/4104.0, 0},
        {-8.0/27.0, 2.0, -3544.0/2565.0, 1859.0/4104.0, -11.0/40.0},
    };
    static const double bcoef[6] = {
        16.0/135.0, 0.0, 6656.0/12825.0, 28561.0/56430.0, -9.0/50.0, 2.0/55.0
    };

    q0_kernel<<<256, 256>>>(x, Wq, bq, Wk, bk, Wv, bv);

    for (int step = 0; step < 4; step++) {
        for (int st = 0; st < 6; st++) {
            attn_kernel<<<512, 256>>>();
            StageCtl ctl;
            ctl.stage = st;
            if (st < 5) {
                ctl.nc = st + 1;
                for (int c = 0; c < 6; c++)
                    ctl.ac[c] = (c <= st)
                        ? (float)((double)DT_F * acoef[st + 1][c]) : 0.f;
                ctl.do_qkv  = 1;
                ctl.write_y = 0;
            } else {
                ctl.nc = 6;
                for (int c = 0; c < 6; c++)
                    ctl.ac[c] = (float)((double)DT_F * bcoef[c]);
                ctl.write_y = 1;
                ctl.do_qkv  = (step < 3) ? 1 : 0;
            }
            fused_kernel<<<512, 256>>>(Wo, bo, W1, b1, W2, b2,
                                       Wq, bq, Wk, bk, Wv, bv, ctl);
        }
    }

    copy_out_kernel<<<128, 256>>>((float*)d_out);
}

// round 7
// speedup vs baseline: 1.3913x; 1.0020x over previous
#include <cuda_runtime.h>

typedef unsigned long long u64;

#define NB   4
#define SS   512
#define DD   64
#define NH   8
#define NROWS (NB*SS)      // 2048
#define DT_F 0.25f
#define PSTR 12            // floats per attention partial record

// Persistent device scratch (no allocations allowed)
__device__ __align__(16) float g_y[NROWS*DD];
__device__ __align__(16) float g_ytmp[NROWS*DD];
__device__ __align__(16) float g_kst[6*NROWS*DD];
__device__ __align__(16) float g_q[NROWS*DD];
__device__ __align__(16) float g_kk[NROWS*DD];
__device__ __align__(16) float g_vv[NROWS*DD];
// attention partials: [bh][s][half][{o0..o7, m, l, pad, pad}]
__device__ __align__(16) float g_attp[32*SS*2*PSTR];

struct StageCtl {
    float ac[6];
    int   nc;
    int   stage;
    int   do_qkv;
    int   write_y;
};

// ---------------- f32x2 helpers ----------------
__device__ __forceinline__ u64 pk(float x, float y) {
    u64 r; asm("mov.b64 %0,{%1,%2};" : "=l"(r) : "f"(x), "f"(y)); return r;
}
__device__ __forceinline__ void unpk(u64 v, float& x, float& y) {
    asm("mov.b64 {%0,%1},%2;" : "=f"(x), "=f"(y) : "l"(v));
}
__device__ __forceinline__ u64 splat(float x) {
    u64 r; asm("mov.b64 %0,{%1,%1};" : "=l"(r) : "f"(x)); return r;
}
__device__ __forceinline__ void fma2(u64& d, u64 a, u64 b) {
    asm("fma.rn.f32x2 %0,%1,%2,%0;" : "+l"(d) : "l"(a), "l"(b));
}
__device__ __forceinline__ u64 add2(u64 a, u64 b) {
    u64 d; asm("add.rn.f32x2 %0,%1,%2;" : "=l"(d) : "l"(a), "l"(b)); return d;
}
__device__ __forceinline__ float elem(u64 v, int h) {
    float x, y; unpk(v, x, y); return h ? y : x;
}

// ---------------------------------------------------------------------------
__global__ void __launch_bounds__(256) copy_out_kernel(float* __restrict__ out) {
    int i = blockIdx.x * blockDim.x + threadIdx.x;
    ((float4*)out)[i] = ((const float4*)g_y)[i];
}

// ---------------------------------------------------------------------------
// qkv GEMV for q0 only: row-pair packed activations sX2 ([4 pairs][64]).
__device__ __forceinline__ void qkv_phase_q0(
    const u64* sX2, int r0,
    const float* __restrict__ Wq, const float* __restrict__ bq,
    const float* __restrict__ Wk, const float* __restrict__ bk,
    const float* __restrict__ Wv, const float* __restrict__ bv)
{
    const int tid = threadIdx.x;
    const int p = tid >> 6, c = tid & 63;
    const u64* xp = sX2 + p * 64;

    u64 aq = 0, ak = 0, av = 0;
#pragma unroll 8
    for (int i = 0; i < 64; i++) {
        u64 x2 = xp[i];
        fma2(aq, x2, splat(__ldg(Wq + i * 64 + c)));
        fma2(ak, x2, splat(__ldg(Wk + i * 64 + c)));
        fma2(av, x2, splat(__ldg(Wv + i * 64 + c)));
    }
    const float scl = 0.35355339059327373f;
    float bqc = __ldg(bq + c), bkc = __ldg(bk + c), bvc = __ldg(bv + c);
    float qx, qy, kx, ky, vx, vy;
    unpk(aq, qx, qy); unpk(ak, kx, ky); unpk(av, vx, vy);
    qx = (qx + bqc) * scl; qy = (qy + bqc) * scl;
    kx += bkc; ky += bkc; vx += bvc; vy += bvc;

    const int h = c >> 3, jj = c & 7;
#pragma unroll
    for (int rr = 0; rr < 2; rr++) {
        int r = r0 + 2 * p + rr;
        int b = r >> 9, s = r & 511;
        int base = ((b * NH + h) * SS + s) * 8 + jj;
        g_q[base]  = rr ? qy : qx;
        g_kk[base] = rr ? ky : kx;
        g_vv[base] = rr ? vy : vx;
    }
}

__global__ void __launch_bounds__(256) q0_kernel(
    const float* __restrict__ x,
    const float* __restrict__ Wq, const float* __restrict__ bq,
    const float* __restrict__ Wk, const float* __restrict__ bk,
    const float* __restrict__ Wv, const float* __restrict__ bv)
{
    __shared__ u64 sX2[4 * 64];
    const int tid = threadIdx.x;
    const int p = tid >> 6, c = tid & 63;
    const int r0 = blockIdx.x * 8;
    {
        int i0 = (r0 + 2 * p) * 64 + c;
        float a = x[i0], b = x[i0 + 64];
        g_y[i0] = a;    g_y[i0 + 64] = b;
        g_ytmp[i0] = a; g_ytmp[i0 + 64] = b;
        sX2[p * 64 + c] = pk(a, b);
    }
    __syncthreads();
    qkv_phase_q0(sX2, r0, Wq, bq, Wk, bk, Wv, bv);
}

// ---------------------------------------------------------------------------
// Attention with key-halving across blocks.
// grid 512 = bh(32) x qtile(8) x half(2); block 256.
// Block handles 64 queries x 256 keys; 4 threads/query (key quarters).
// Emits unnormalized partial {o[8], m, l} to g_attp.
__global__ void __launch_bounds__(256) attn_kernel()
{
    __shared__ float4 ks[256 * 2];   // 8KB
    __shared__ float4 vs[256 * 2];   // 8KB

    const int blk = blockIdx.x;
    const int half = blk & 1;
    const int qt  = (blk >> 1) & 7;
    const int bh  = blk >> 4;
    const int tid = threadIdx.x;

    const float4* kg = (const float4*)g_kk + (bh * SS + half * 256) * 2;
    const float4* vg = (const float4*)g_vv + (bh * SS + half * 256) * 2;
    for (int i = tid; i < 256 * 2; i += 256) { ks[i] = kg[i]; vs[i] = vg[i]; }
    __syncthreads();

    const int lane = tid & 31;
    const int warp = tid >> 5;
    const int quarter = lane >> 3;
    const int qg = qt * 64 + warp * 8 + (lane & 7);

    const float4* qp = (const float4*)g_q + (bh * SS + qg) * 2;
    const float4 q0 = qp[0];
    const float4 q1 = qp[1];

    float m = -1e30f, l = 0.f;
    float o[8];
#pragma unroll
    for (int j = 0; j < 8; j++) o[j] = 0.f;

    const int t0 = quarter * 64;
#pragma unroll 2
    for (int i = 0; i < 64; i++) {
        const int t = t0 + i;
        float4 ka = ks[2 * t], kb = ks[2 * t + 1];
        float s = q0.x * ka.x + q0.y * ka.y + q0.z * ka.z + q0.w * ka.w
                + q1.x * kb.x + q1.y * kb.y + q1.z * kb.z + q1.w * kb.w;
        if (s > m) {
            float corr = __expf(m - s);
            l *= corr;
#pragma unroll
            for (int j = 0; j < 8; j++) o[j] *= corr;
            m = s;
        }
        float p = __expf(s - m);
        l += p;
        float4 va = vs[2 * t], vb = vs[2 * t + 1];
        o[0] += p * va.x; o[1] += p * va.y; o[2] += p * va.z; o[3] += p * va.w;
        o[4] += p * vb.x; o[5] += p * vb.y; o[6] += p * vb.z; o[7] += p * vb.w;
    }

    // merge 4 key-quarters (lanes l, l^8, l^16, l^24 share a query)
#pragma unroll
    for (int d = 8; d <= 16; d <<= 1) {
        float m2 = __shfl_xor_sync(0xffffffffu, m, d);
        float l2 = __shfl_xor_sync(0xffffffffu, l, d);
        float M  = fmaxf(m, m2);
        float sA = __expf(m - M);
        float sB = __expf(m2 - M);
        l = l * sA + l2 * sB;
#pragma unroll
        for (int j = 0; j < 8; j++) {
            float o2 = __shfl_xor_sync(0xffffffffu, o[j], d);
            o[j] = o[j] * sA + o2 * sB;
        }
        m = M;
    }

    if (quarter == 0) {
        float* dst = g_attp + ((bh * SS + qg) * 2 + half) * PSTR;
        *(float4*)(dst)     = make_float4(o[0], o[1], o[2], o[3]);
        *(float4*)(dst + 4) = make_float4(o[4], o[5], o[6], o[7]);
        *(float4*)(dst + 8) = make_float4(m, l, 0.f, 0.f);
    }
}

// ---------------------------------------------------------------------------
// Fused: merge attn partials -> att; out-proj + residual + FFN -> k[stage];
// RK combo -> ytmp (or y); next-stage qkv.
// grid 512, block 256, 4 rows/block. Thread = (h2 = dot-half, p = row-pair, c).
// Activations stored as [i][4 rows] floats; pair reads = broadcast LDS.64.
__global__ void __launch_bounds__(256) fused_kernel(
    const float* __restrict__ Wo, const float* __restrict__ bo,
    const float* __restrict__ W1, const float* __restrict__ b1,
    const float* __restrict__ W2, const float* __restrict__ b2,
    const float* __restrict__ Wq, const float* __restrict__ bq,
    const float* __restrict__ Wk, const float* __restrict__ bk,
    const float* __restrict__ Wv, const float* __restrict__ bv,
    StageCtl ctl)
{
    __shared__ float sAf[64 * 4];     // att  [i][row]
    __shared__ float sHf[64 * 4];     // h    [i][row]
    __shared__ float sUf[256 * 4];    // relu [i][row]
    __shared__ float sXf[64 * 4];     // combined state [i][row]
    __shared__ u64 sPB[2 * 128];      // dot-half partials (B/D reuse)
    __shared__ u64 sPC[2 * 512];      // C partials; F reuses as 3x[2][128]

    const int tid = threadIdx.x;
    const int h2 = tid >> 7;          // dot-half
    const int p  = (tid >> 6) & 1;    // row-pair within block
    const int c  = tid & 63;
    const int r0 = blockIdx.x * 4;
    const int rA = r0 + 2 * p;        // pair's first row
    const int rME = rA + h2;          // row this thread owns for scalar phases

    // ---- Phase A: merge attention halves -> att value for row rME, col c ----
    {
        const int h = c >> 3, jj = c & 7;
        const int b = rME >> 9, s = rME & 511;
        const float* pp = g_attp + (((b * NH + h) * SS + s) * 2) * PSTR;
        float o0 = pp[jj], m0 = pp[8], l0 = pp[9];
        float o1 = pp[PSTR + jj], m1 = pp[PSTR + 8], l1 = pp[PSTR + 9];
        float M = fmaxf(m0, m1);
        float w0 = __expf(m0 - M), w1 = __expf(m1 - M);
        float att = (w0 * o0 + w1 * o1) / (w0 * l0 + w1 * l1);
        sAf[c * 4 + 2 * p + h2] = att;
    }
    __syncthreads();

    // ---- Phase B: out projection (Wo) ----
    u64 o1v;
    {
        u64 acc = 0;
        const int i0 = 32 * h2;
        const float2* ap = (const float2*)sAf;
#pragma unroll 8
        for (int i = i0; i < i0 + 32; i++) {
            float2 a2 = ap[i * 2 + p];
            fma2(acc, pk(a2.x, a2.y), splat(__ldg(Wo + i * 64 + c)));
        }
        sPB[h2 * 128 + p * 64 + c] = acc;
    }
    __syncthreads();
    {
        o1v = add2(add2(sPB[p * 64 + c], sPB[128 + p * 64 + c]),
                   splat(__ldg(bo + c)));
        // residual for row rME
        float hv = g_ytmp[rME * 64 + c] + elem(o1v, h2);
        sHf[c * 4 + 2 * p + h2] = hv;
    }
    __syncthreads();

    // ---- Phase C: hidden layer (W1) + relu ----
    {
        u64 u[4] = {0, 0, 0, 0};
        const int i0 = 32 * h2;
        const float2* hp = (const float2*)sHf;
#pragma unroll 4
        for (int i = i0; i < i0 + 32; i++) {
            float2 h2v = hp[i * 2 + p];
            u64 hx = pk(h2v.x, h2v.y);
            const float* wrow = W1 + i * 256 + c;
            fma2(u[0], hx, splat(__ldg(wrow)));
            fma2(u[1], hx, splat(__ldg(wrow + 64)));
            fma2(u[2], hx, splat(__ldg(wrow + 128)));
            fma2(u[3], hx, splat(__ldg(wrow + 192)));
        }
#pragma unroll
        for (int k = 0; k < 4; k++)
            sPC[(h2 * 2 + p) * 256 + c + 64 * k] = u[k];
    }
    __syncthreads();
    {
#pragma unroll
        for (int k = 0; k < 4; k++) {
            int col = c + 64 * k;
            u64 s2 = add2(sPC[p * 256 + col], sPC[512 + p * 256 + col]);
            float b1c = __ldg(b1 + col);
            sUf[col * 4 + 2 * p + h2] = fmaxf(elem(s2, h2) + b1c, 0.f);
        }
    }
    __syncthreads();

    // ---- Phase D: second FFN layer (W2) ----
    u64 kv2;
    {
        u64 acc0 = 0, acc1 = 0;
        const int i0 = 128 * h2;
        const float2* up = (const float2*)sUf;
#pragma unroll 8
        for (int i = i0; i < i0 + 128; i += 2) {
            float2 ua = up[i * 2 + p];
            float2 ub = up[(i + 1) * 2 + p];
            fma2(acc0, pk(ua.x, ua.y), splat(__ldg(W2 + i * 64 + c)));
            fma2(acc1, pk(ub.x, ub.y), splat(__ldg(W2 + (i + 1) * 64 + c)));
        }
        sPB[h2 * 128 + p * 64 + c] = add2(acc0, acc1);
    }
    __syncthreads();
    {
        u64 f2 = add2(sPB[p * 64 + c], sPB[128 + p * 64 + c]);
        kv2 = add2(o1v, add2(f2, splat(__ldg(b2 + c))));
        g_kst[(ctl.stage * NROWS + rME) * 64 + c] = elem(kv2, h2);
    }

    // ---- Phase E: RK combination (scalar, row rME) ----
    {
        float v = g_y[rME * 64 + c];
        float kme = elem(kv2, h2);
        for (int cc = 0; cc < ctl.nc; cc++) {
            float kx = (cc == ctl.stage) ? kme
                     : g_kst[(cc * NROWS + rME) * 64 + c];
            v = fmaf(ctl.ac[cc], kx, v);
        }
        if (ctl.write_y) g_y[rME * 64 + c] = v;
        g_ytmp[rME * 64 + c] = v;
        sXf[c * 4 + 2 * p + h2] = v;
    }
    __syncthreads();

    // ---- Phase F: next-stage qkv ----
    if (ctl.do_qkv) {
        u64 aq = 0, ak = 0, av = 0;
        const int i0 = 32 * h2;
        const float2* xp = (const float2*)sXf;
#pragma unroll 8
        for (int i = i0; i < i0 + 32; i++) {
            float2 x2 = xp[i * 2 + p];
            u64 xx = pk(x2.x, x2.y);
            fma2(aq, xx, splat(__ldg(Wq + i * 64 + c)));
            fma2(ak, xx, splat(__ldg(Wk + i * 64 + c)));
            fma2(av, xx, splat(__ldg(Wv + i * 64 + c)));
        }
        u64* sQ = sPC;          // [2][128]
        u64* sK = sPC + 256;    // [2][128]
        u64* sV = sPC + 512;    // [2][128]
        sQ[h2 * 128 + p * 64 + c] = aq;
        sK[h2 * 128 + p * 64 + c] = ak;
        sV[h2 * 128 + p * 64 + c] = av;
        __syncthreads();

        const float scl = 0.35355339059327373f;
        float qv = (elem(add2(sQ[p * 64 + c], sQ[128 + p * 64 + c]), h2)
                    + __ldg(bq + c)) * scl;
        float kv = elem(add2(sK[p * 64 + c], sK[128 + p * 64 + c]), h2)
                    + __ldg(bk + c);
        float vv = elem(add2(sV[p * 64 + c], sV[128 + p * 64 + c]), h2)
                    + __ldg(bv + c);

        const int h = c >> 3, jj = c & 7;
        const int b = rME >> 9, s = rME & 511;
        int base = ((b * NH + h) * SS + s) * 8 + jj;
        g_q[base]  = qv;
        g_kk[base] = kv;
        g_vv[base] = vv;
    }
}

// ---------------------------------------------------------------------------
extern "C" void kernel_launch(void* const* d_in, const int* in_sizes, int n_in,
                              void* d_out, int out_size)
{
    (void)in_sizes; (void)n_in; (void)out_size;

    const float* x  = (const float*)d_in[0];
    // d_in[1] = mask: broadcasts over key axis -> softmax-invariant; ignored.
    const float* Wq = (const float*)d_in[2];
    const float* bq = (const float*)d_in[3];
    const float* Wk = (const float*)d_in[4];
    const float* bk = (const float*)d_in[5];
    const float* Wv = (const float*)d_in[6];
    const float* bv = (const float*)d_in[7];
    const float* Wo = (const float*)d_in[8];
    const float* bo = (const float*)d_in[9];
    const float* W1 = (const float*)d_in[10];
    const float* b1 = (const float*)d_in[11];
    const float* W2 = (const float*)d_in[12];
    const float* b2 = (const float*)d_in[13];

    static const double acoef[6][5] = {
        {0, 0, 0, 0, 0},
        {0.25, 0, 0, 0, 0},
        {3.0/32.0, 9.0/32.0, 0, 0, 0},
        {1932.0/2197.0, -7200.0/2197.0, 7296.0/2197.0, 0, 0},
        {439.0/216.0, -8.0, 3680.0/513.0, -845.0/4104.0, 0},
        {-8.0/27.0, 2.0, -3544.0/2565.0, 1859.0/4104.0, -11.0/40.0},
    };
    static const double bcoef[6] = {
        16.0/135.0, 0.0, 6656.0/12825.0, 28561.0/56430.0, -9.0/50.0, 2.0/55.0
    };

    q0_kernel<<<256, 256>>>(x, Wq, bq, Wk, bk, Wv, bv);

    for (int step = 0; step < 4; step++) {
        for (int st = 0; st < 6; st++) {
            attn_kernel<<<512, 256>>>();
            StageCtl ctl;
            ctl.stage = st;
            if (st < 5) {
                ctl.nc = st + 1;
                for (int c = 0; c < 6; c++)
                    ctl.ac[c] = (c <= st)
                        ? (float)((double)DT_F * acoef[st + 1][c]) : 0.f;
                ctl.do_qkv  = 1;
                ctl.write_y = 0;
            } else {
                ctl.nc = 6;
                for (int c = 0; c < 6; c++)
                    ctl.ac[c] = (float)((double)DT_F * bcoef[c]);
                ctl.write_y = 1;
                ctl.do_qkv  = (step < 3) ? 1 : 0;
            }
            fused_kernel<<<512, 256>>>(Wo, bo, W1, b1, W2, b2,
                                       Wq, bq, Wk, bk, Wv, bv, ctl);
        }
    }

    copy_out_kernel<<<128, 256>>>((float*)d_out);
}